// round 9
// baseline (speedup 1.0000x reference)
#include <cuda_runtime.h>
#include <cuda_fp16.h>

#define NN 100000
#define NE 1200000
#define SCAN_B 98      // ceil(NN / 1024)
#define HSPLIT 50048   // node split point; multiple of 128 (gemm tile sizes)

// ---------------- device scratch (no allocations allowed) ----------------
// g_cnt / g_bval are zero at module load; k_scan re-zeroes g_cnt and k_fill
// re-zeroes g_bval each call, so every graph replay starts from clean state.
__device__ int                g_cnt[NN];
__device__ float              g_dinv[NN];
__device__ int                g_rowptr[NN + 1];
__device__ int2               g_nodei[NN];         // {rowptr, dinv-as-int} for fill
__device__ int                g_rank[NE];          // within-bucket rank of each edge
__device__ int2               g_edge[NE];          // {src, norm-as-int}
__device__ unsigned long long g_bval[SCAN_B];      // packed (flag<<32 | blocksum)
__device__ __half             g_bufh[NN * 64];     // x @ W1      (gather1 operand)
__device__ __half             g_buf2[NN * 64];     // h1 agg      -> gemm2 in; later gather2 out
__device__ __half             g_bufc[NN * 64];     // h1 @ W2     (gather2 operand)

// packed f32x2 FMA (sm_103a FFMA2; 2x fp32 FMA throughput)
#define FMA_F32X2(d, a, b, c) \
    asm("fma.rn.f32x2 %0, %1, %2, %3;" : "=l"(d) : "l"(a), "l"(b), "l"(c))
#define PACK_F32X2(out, lo, hi) \
    asm("mov.b64 %0, {%1, %2};" : "=l"(out) : "f"(lo), "f"(hi))
#define UNPACK_F32X2(lo, hi, in) \
    asm("mov.b64 {%0, %1}, %2;" : "=f"(lo), "=f"(hi) : "l"(in))

// ---------------- per-block dtype probe (first 128 values, L2-hit) ----------------
__device__ __forceinline__ int probe_is64(const int* __restrict__ raw) {
    __shared__ int s_is64;
    if (threadIdx.x < 32) {
        bool ok = true;
#pragma unroll
        for (int k = 0; k < 4; k++) {
            int idx = threadIdx.x * 4 + k;
            ok &= (raw[2 * idx + 1] == 0) && ((unsigned)raw[2 * idx] < NN);
        }
        unsigned m = __ballot_sync(~0u, ok);
        if (threadIdx.x == 0) s_is64 = (m == ~0u) ? 1 : 0;
    }
    __syncthreads();
    return s_is64;
}

__device__ __forceinline__ int edge_at(const int* raw, int idx, int is64) {
    return is64 ? (int)((const long long*)raw)[idx] : raw[idx];
}

// ---------------- count + rank (no predecessors) ----------------
__global__ void k_count(const int* __restrict__ raw) {
    int is64 = probe_is64(raw);
    int e = blockIdx.x * blockDim.x + threadIdx.x;
    if (e >= NE) return;
    int d = edge_at(raw, NE + e, is64);
    int r = 0;
    if ((unsigned)d < NN) r = atomicAdd(&g_cnt[d], 1);
    g_rank[e] = r;
}

// ---------------- single-kernel scan (98 blocks co-resident, decoupled lookback) ----
__global__ void __launch_bounds__(1024) k_scan() {
    __shared__ int wsum[32];
    __shared__ int s_boff;
    int tid = threadIdx.x;
    int lane = tid & 31, wid = tid >> 5;
    int i = blockIdx.x * 1024 + tid;
    int c = (i < NN) ? g_cnt[i] : 0;
    float dv = rsqrtf((float)c + 1.0f);
    if (i < NN) {
        g_dinv[i] = dv;
        g_cnt[i] = 0;                          // reset for next replay
    }

    int incl = c;
#pragma unroll
    for (int o = 1; o < 32; o <<= 1) {
        int t = __shfl_up_sync(~0u, incl, o);
        if (lane >= o) incl += t;
    }
    if (lane == 31) wsum[wid] = incl;
    __syncthreads();
    if (tid < 32) {
        int w = wsum[tid];
        int iw = w;
#pragma unroll
        for (int o = 1; o < 32; o <<= 1) {
            int t = __shfl_up_sync(~0u, iw, o);
            if (tid >= o) iw += t;
        }
        wsum[tid] = iw - w;                    // exclusive warp offset
        if (tid == 31)                         // publish block aggregate
            atomicExch(&g_bval[blockIdx.x], (1ull << 32) | (unsigned)iw);
    }
    __syncthreads();

    if (wid == 0) {
        int my = blockIdx.x;
        unsigned acc = 0;
        for (int base = 0; base < my; base += 32) {
            int j = base + lane;
            if (j < my) {
                unsigned long long v;
                do { v = atomicAdd(&g_bval[j], 0ull); } while ((v >> 32) == 0);
                acc += (unsigned)v;
            }
        }
#pragma unroll
        for (int o = 16; o; o >>= 1) acc += __shfl_down_sync(~0u, acc, o);
        if (lane == 0) s_boff = (int)acc;
    }
    __syncthreads();

    if (i < NN) {
        int excl = incl - c + wsum[wid] + s_boff;
        g_rowptr[i] = excl;
        g_nodei[i] = make_int2(excl, __float_as_int(dv));   // packed for fill
    }
    if (blockIdx.x == 0 && tid == 0) g_rowptr[NN] = NE;
}

// ---------------- fill CSR: atomic-free; one packed random read for dst ----------------
__global__ void k_fill(const int* __restrict__ raw) {
    int is64 = probe_is64(raw);
    if (blockIdx.x == 0 && threadIdx.x < SCAN_B) g_bval[threadIdx.x] = 0ull;
    int e = blockIdx.x * blockDim.x + threadIdx.x;
    if (e >= NE) return;
    int s = edge_at(raw, e, is64);
    int d = edge_at(raw, NE + e, is64);
    if ((unsigned)s >= NN || (unsigned)d >= NN) return;
    int2 nd = g_nodei[d];                      // {rowptr[d], dinv[d]}
    int pos = nd.x + g_rank[e];
    float norm = g_dinv[s] * __int_as_float(nd.y);
    g_edge[pos] = make_int2(s, __float_as_int(norm));
}

// ---------------- stores ----------------
__device__ __forceinline__ void store4(float* p, float a, float b, float c, float d) {
    *(float4*)p = make_float4(a, b, c, d);
}
__device__ __forceinline__ void store4(__half* p, float a, float b, float c, float d) {
    *(__half2*)p = __floats2half2_rn(a, b);
    *(__half2*)(p + 2) = __floats2half2_rn(c, d);
}

// ---------------- dense GEMM over tile range: out[N,NC] = in[N,64] @ W[64,NC] (+bias) --
template <int NC, typename InT, typename OutT, bool BIAS>
__global__ void __launch_bounds__(256) k_gemm(const InT* __restrict__ in,
                                              const float* __restrict__ W,
                                              const float* __restrict__ bias,
                                              OutT* __restrict__ out,
                                              int tile0, int tileEnd) {
    constexpr int CG = NC / 4;
    constexpr int RQ = 256 / CG;
    constexpr int TM = RQ * 4;
    constexpr int XP = 65;
    __shared__ float Ws[64 * NC];
    __shared__ float Xs[TM * XP];

    for (int i = threadIdx.x; i < 64 * NC; i += 256) Ws[i] = W[i];

    int rq = threadIdx.x / CG;
    int cg = threadIdx.x % CG;

    for (int tile = tile0 + blockIdx.x; tile < tileEnd; tile += gridDim.x) {
        int row0 = tile * TM;
        int nr = min(TM, NN - row0);
        __syncthreads();
        if constexpr (sizeof(InT) == 4) {
            const float* src = (const float*)in + row0 * 64;
            for (int i = threadIdx.x; i < nr * 64; i += 256)
                Xs[(i >> 6) * XP + (i & 63)] = src[i];
        } else {
            const __half2* src = (const __half2*)((const __half*)in + row0 * 64);
            for (int i = threadIdx.x; i < nr * 32; i += 256) {
                float2 f = __half22float2(src[i]);
                int r = i >> 5, c = (i & 31) * 2;
                Xs[r * XP + c] = f.x;
                Xs[r * XP + c + 1] = f.y;
            }
        }
        __syncthreads();

        unsigned long long acc[4][2] = {};
#pragma unroll 4
        for (int k = 0; k < 64; k++) {
            ulonglong2 w = *(const ulonglong2*)&Ws[k * NC + cg * 4];
#pragma unroll
            for (int r = 0; r < 4; r++) {
                float xv = Xs[(rq * 4 + r) * XP + k];
                unsigned long long xx;
                PACK_F32X2(xx, xv, xv);
                FMA_F32X2(acc[r][0], xx, w.x, acc[r][0]);
                FMA_F32X2(acc[r][1], xx, w.y, acc[r][1]);
            }
        }
        float4 bv = make_float4(0.f, 0.f, 0.f, 0.f);
        if (BIAS) bv = *(const float4*)&bias[cg * 4];
#pragma unroll
        for (int r = 0; r < 4; r++) {
            int row = row0 + rq * 4 + r;
            if (row < NN) {
                float f0, f1, f2, f3;
                UNPACK_F32X2(f0, f1, acc[r][0]);
                UNPACK_F32X2(f2, f3, acc[r][1]);
                store4(&out[row * NC + cg * 4],
                       f0 + bv.x, f1 + bv.y, f2 + bv.z, f3 + bv.w);
            }
        }
    }
}

// ---------------- aggregate over node range ----------------
__global__ void __launch_bounds__(256) k_gather(const __half2* __restrict__ hw,
                                                const float* __restrict__ bias,
                                                __half2* __restrict__ hout,
                                                int n0, int n1) {
    int node = n0 + blockIdx.x * 8 + (threadIdx.x >> 5);
    if (node >= n1) return;
    int lane = threadIdx.x & 31;

    float di = g_dinv[node];
    float self = di * di;
    float2 v = __half22float2(__ldg(&hw[node * 32 + lane]));
    float ax = self * v.x, ay = self * v.y;

    int beg = g_rowptr[node], end = g_rowptr[node + 1];
    int j = beg;
    for (; j + 4 <= end; j += 4) {
        int2 e0 = __ldg(&g_edge[j]);
        int2 e1 = __ldg(&g_edge[j + 1]);
        int2 e2 = __ldg(&g_edge[j + 2]);
        int2 e3 = __ldg(&g_edge[j + 3]);
        float2 u0 = __half22float2(__ldg(&hw[e0.x * 32 + lane]));
        float2 u1 = __half22float2(__ldg(&hw[e1.x * 32 + lane]));
        float2 u2 = __half22float2(__ldg(&hw[e2.x * 32 + lane]));
        float2 u3 = __half22float2(__ldg(&hw[e3.x * 32 + lane]));
        float w0 = __int_as_float(e0.y), w1 = __int_as_float(e1.y);
        float w2 = __int_as_float(e2.y), w3 = __int_as_float(e3.y);
        ax = fmaf(w0, u0.x, ax); ay = fmaf(w0, u0.y, ay);
        ax = fmaf(w1, u1.x, ax); ay = fmaf(w1, u1.y, ay);
        ax = fmaf(w2, u2.x, ax); ay = fmaf(w2, u2.y, ay);
        ax = fmaf(w3, u3.x, ax); ay = fmaf(w3, u3.y, ay);
    }
    for (; j < end; j++) {
        int2 e = __ldg(&g_edge[j]);
        float2 u = __half22float2(__ldg(&hw[e.x * 32 + lane]));
        float w = __int_as_float(e.y);
        ax = fmaf(w, u.x, ax); ay = fmaf(w, u.y, ay);
    }
    float2 b = ((const float2*)bias)[lane];
    ax = fmaxf(ax + b.x, 0.f);
    ay = fmaxf(ay + b.y, 0.f);
    hout[node * 32 + lane] = __floats2half2_rn(ax, ay);
}

// ---------------- launch ----------------
extern "C" void kernel_launch(void* const* d_in, const int* in_sizes, int n_in,
                              void* d_out, int out_size) {
    const float* x  = (const float*)d_in[0];
    const int*   ei = (const int*)d_in[1];
    const float* W1 = (const float*)d_in[2];
    const float* b1 = (const float*)d_in[3];
    const float* W2 = (const float*)d_in[4];
    const float* b2 = (const float*)d_in[5];
    const float* Wl = (const float*)d_in[6];
    const float* bl = (const float*)d_in[7];
    float*       out = (float*)d_out;

    __half* bufh; cudaGetSymbolAddress((void**)&bufh, g_bufh);
    __half* buf2; cudaGetSymbolAddress((void**)&buf2, g_buf2);
    __half* bufc; cudaGetSymbolAddress((void**)&bufc, g_bufc);

    static cudaStream_t s2 = nullptr;
    static cudaEvent_t evFork = nullptr, evJoin = nullptr;
    static cudaEvent_t evA = nullptr, evB = nullptr, evC = nullptr, evD = nullptr;
    if (s2 == nullptr) {
        cudaStreamCreateWithFlags(&s2, cudaStreamNonBlocking);
        cudaEventCreateWithFlags(&evFork, cudaEventDisableTiming);
        cudaEventCreateWithFlags(&evJoin, cudaEventDisableTiming);
        cudaEventCreateWithFlags(&evA, cudaEventDisableTiming);
        cudaEventCreateWithFlags(&evB, cudaEventDisableTiming);
        cudaEventCreateWithFlags(&evC, cudaEventDisableTiming);
        cudaEventCreateWithFlags(&evD, cudaEventDisableTiming);
    }

    const int TB = 256;
    int gE = (NE + TB - 1) / TB;
    const int GEMM_GRID = 296;

    // tile ranges (TM=64 for NC=64; TM=128 for NC=32); HSPLIT divisible by both
    const int T64_H = HSPLIT / 64;                 // 782
    const int T64_E = (NN + 63) / 64;              // 1563
    const int T32_H = HSPLIT / 128;                // 391
    const int T32_E = (NN + 127) / 128;            // 782
    const int GA_H1 = (HSPLIT + 7) / 8;
    const int GA_H2 = (NN - HSPLIT + 7) / 8;

    // fork: GEMM1 (x @ W1, full) independent of the CSR build
    cudaEventRecord(evFork, 0);
    cudaStreamWaitEvent(s2, evFork, 0);
    k_gemm<64, float, __half, false><<<GEMM_GRID, 256, 0, s2>>>(x, W1, nullptr, bufh, 0, T64_E);
    cudaEventRecord(evJoin, s2);

    // CSR build (concurrent with GEMM1)
    k_count<<<gE, TB>>>(ei);
    k_scan<<<SCAN_B, 1024>>>();
    k_fill<<<gE, TB>>>(ei);

    // layer 1 gather, half-split pipeline with gemm2
    cudaStreamWaitEvent(0, evJoin, 0);
    k_gather<<<GA_H1, 256>>>((const __half2*)bufh, b1, (__half2*)buf2, 0, HSPLIT);
    cudaEventRecord(evA, 0);
    cudaStreamWaitEvent(s2, evA, 0);
    k_gemm<64, __half, __half, false><<<GEMM_GRID, 256, 0, s2>>>(buf2, W2, nullptr, bufc, 0, T64_H);
    cudaEventRecord(evB, s2);
    k_gather<<<GA_H2, 256>>>((const __half2*)bufh, b1, (__half2*)buf2, HSPLIT, NN);
    k_gemm<64, __half, __half, false><<<GEMM_GRID, 256>>>(buf2, W2, nullptr, bufc, T64_H, T64_E);

    // layer 2 gather, half-split pipeline with gemm3
    cudaStreamWaitEvent(0, evB, 0);
    k_gather<<<GA_H1, 256>>>((const __half2*)bufc, b2, (__half2*)buf2, 0, HSPLIT);
    cudaEventRecord(evC, 0);
    cudaStreamWaitEvent(s2, evC, 0);
    k_gemm<32, __half, float, true><<<GEMM_GRID, 256, 0, s2>>>(buf2, Wl, bl, out, 0, T32_H);
    cudaEventRecord(evD, s2);
    k_gather<<<GA_H2, 256>>>((const __half2*)bufc, b2, (__half2*)buf2, HSPLIT, NN);
    k_gemm<32, __half, float, true><<<GEMM_GRID, 256>>>(buf2, Wl, bl, out, T32_H, T32_E);
    cudaStreamWaitEvent(0, evD, 0);
}

// round 10
// speedup vs baseline: 1.0847x; 1.0847x over previous
#include <cuda_runtime.h>
#include <cuda_fp16.h>

#define NN 100000
#define NE 1200000
#define SCAN_B 98   // ceil(NN / 1024)

// ---------------- device scratch (no allocations allowed) ----------------
// g_cnt / g_bval are zero at module load; k_scan re-zeroes g_cnt and k_fill
// re-zeroes g_bval each call, so every graph replay starts from clean state.
__device__ int                g_cnt[NN];
__device__ float              g_dinv[NN];
__device__ int                g_rowptr[NN + 1];
__device__ int2               g_nodei[NN];         // {rowptr, dinv-as-int} for fill
__device__ int                g_rank[NE];          // within-bucket rank of each edge
__device__ int2               g_edge[NE];          // {src, norm-as-int}
__device__ unsigned long long g_bval[SCAN_B];      // packed (flag<<32 | blocksum)
__device__ __half             g_bufh[NN * 64];     // transformed features (gather operand)
__device__ __half             g_buf2[NN * 64];     // aggregated hidden state

// packed f32x2 FMA (sm_103a FFMA2; 2x fp32 FMA throughput)
#define FMA_F32X2(d, a, b, c) \
    asm("fma.rn.f32x2 %0, %1, %2, %3;" : "=l"(d) : "l"(a), "l"(b), "l"(c))
#define PACK_F32X2(out, lo, hi) \
    asm("mov.b64 %0, {%1, %2};" : "=l"(out) : "f"(lo), "f"(hi))
#define UNPACK_F32X2(lo, hi, in) \
    asm("mov.b64 {%0, %1}, %2;" : "=f"(lo), "=f"(hi) : "l"(in))

// ---------------- per-block dtype probe (first 128 values, L2-hit) ----------------
__device__ __forceinline__ int probe_is64(const int* __restrict__ raw) {
    __shared__ int s_is64;
    if (threadIdx.x < 32) {
        bool ok = true;
#pragma unroll
        for (int k = 0; k < 4; k++) {
            int idx = threadIdx.x * 4 + k;
            ok &= (raw[2 * idx + 1] == 0) && ((unsigned)raw[2 * idx] < NN);
        }
        unsigned m = __ballot_sync(~0u, ok);
        if (threadIdx.x == 0) s_is64 = (m == ~0u) ? 1 : 0;
    }
    __syncthreads();
    return s_is64;
}

__device__ __forceinline__ int edge_at(const int* raw, int idx, int is64) {
    return is64 ? (int)((const long long*)raw)[idx] : raw[idx];
}

// ---------------- count + rank (no predecessors) ----------------
__global__ void k_count(const int* __restrict__ raw) {
    int is64 = probe_is64(raw);
    int e = blockIdx.x * blockDim.x + threadIdx.x;
    if (e >= NE) return;
    int d = edge_at(raw, NE + e, is64);
    int r = 0;
    if ((unsigned)d < NN) r = atomicAdd(&g_cnt[d], 1);
    g_rank[e] = r;
}

// ---------------- single-kernel scan (98 blocks co-resident, decoupled lookback) ----
__global__ void __launch_bounds__(1024) k_scan() {
    __shared__ int wsum[32];
    __shared__ int s_boff;
    int tid = threadIdx.x;
    int lane = tid & 31, wid = tid >> 5;
    int i = blockIdx.x * 1024 + tid;
    int c = (i < NN) ? g_cnt[i] : 0;
    float dv = rsqrtf((float)c + 1.0f);
    if (i < NN) {
        g_dinv[i] = dv;
        g_cnt[i] = 0;                          // reset for next replay
    }

    int incl = c;
#pragma unroll
    for (int o = 1; o < 32; o <<= 1) {
        int t = __shfl_up_sync(~0u, incl, o);
        if (lane >= o) incl += t;
    }
    if (lane == 31) wsum[wid] = incl;
    __syncthreads();
    if (tid < 32) {
        int w = wsum[tid];
        int iw = w;
#pragma unroll
        for (int o = 1; o < 32; o <<= 1) {
            int t = __shfl_up_sync(~0u, iw, o);
            if (tid >= o) iw += t;
        }
        wsum[tid] = iw - w;                    // exclusive warp offset
        if (tid == 31)                         // publish block aggregate
            atomicExch(&g_bval[blockIdx.x], (1ull << 32) | (unsigned)iw);
    }
    __syncthreads();

    if (wid == 0) {
        int my = blockIdx.x;
        unsigned acc = 0;
        for (int base = 0; base < my; base += 32) {
            int j = base + lane;
            if (j < my) {
                unsigned long long v;
                do { v = atomicAdd(&g_bval[j], 0ull); } while ((v >> 32) == 0);
                acc += (unsigned)v;
            }
        }
#pragma unroll
        for (int o = 16; o; o >>= 1) acc += __shfl_down_sync(~0u, acc, o);
        if (lane == 0) s_boff = (int)acc;
    }
    __syncthreads();

    if (i < NN) {
        int excl = incl - c + wsum[wid] + s_boff;
        g_rowptr[i] = excl;
        g_nodei[i] = make_int2(excl, __float_as_int(dv));   // packed for fill
    }
    if (blockIdx.x == 0 && tid == 0) g_rowptr[NN] = NE;
}

// ---------------- fill CSR: atomic-free; one packed random read for dst ----------------
__global__ void k_fill(const int* __restrict__ raw) {
    int is64 = probe_is64(raw);
    if (blockIdx.x == 0 && threadIdx.x < SCAN_B) g_bval[threadIdx.x] = 0ull;
    int e = blockIdx.x * blockDim.x + threadIdx.x;
    if (e >= NE) return;
    int s = edge_at(raw, e, is64);
    int d = edge_at(raw, NE + e, is64);
    if ((unsigned)s >= NN || (unsigned)d >= NN) return;
    int2 nd = g_nodei[d];                      // {rowptr[d], dinv[d]}
    int pos = nd.x + g_rank[e];
    float norm = g_dinv[s] * __int_as_float(nd.y);
    g_edge[pos] = make_int2(s, __float_as_int(norm));
}

// ---------------- stores ----------------
__device__ __forceinline__ void store4(float* p, float a, float b, float c, float d) {
    *(float4*)p = make_float4(a, b, c, d);
}
__device__ __forceinline__ void store4(__half* p, float a, float b, float c, float d) {
    *(__half2*)p = __floats2half2_rn(a, b);
    *(__half2*)(p + 2) = __floats2half2_rn(c, d);
}

// ---------------- dense GEMM: out[N,NC] = in[N,64] @ W[64,NC] (+bias) ----------------
template <int NC, typename InT, typename OutT, bool BIAS>
__global__ void __launch_bounds__(256) k_gemm(const InT* __restrict__ in,
                                              const float* __restrict__ W,
                                              const float* __restrict__ bias,
                                              OutT* __restrict__ out) {
    constexpr int CG = NC / 4;
    constexpr int RQ = 256 / CG;
    constexpr int TM = RQ * 4;
    constexpr int XP = 65;
    __shared__ float Ws[64 * NC];
    __shared__ float Xs[TM * XP];

    for (int i = threadIdx.x; i < 64 * NC; i += 256) Ws[i] = W[i];

    int rq = threadIdx.x / CG;
    int cg = threadIdx.x % CG;
    int ntiles = (NN + TM - 1) / TM;

    for (int tile = blockIdx.x; tile < ntiles; tile += gridDim.x) {
        int row0 = tile * TM;
        int nr = min(TM, NN - row0);
        __syncthreads();
        if constexpr (sizeof(InT) == 4) {
            const float* src = (const float*)in + row0 * 64;
            for (int i = threadIdx.x; i < nr * 64; i += 256)
                Xs[(i >> 6) * XP + (i & 63)] = src[i];
        } else {
            const __half2* src = (const __half2*)((const __half*)in + row0 * 64);
            for (int i = threadIdx.x; i < nr * 32; i += 256) {
                float2 f = __half22float2(src[i]);
                int r = i >> 5, c = (i & 31) * 2;
                Xs[r * XP + c] = f.x;
                Xs[r * XP + c + 1] = f.y;
            }
        }
        __syncthreads();

        unsigned long long acc[4][2] = {};
#pragma unroll 4
        for (int k = 0; k < 64; k++) {
            ulonglong2 w = *(const ulonglong2*)&Ws[k * NC + cg * 4];
#pragma unroll
            for (int r = 0; r < 4; r++) {
                float xv = Xs[(rq * 4 + r) * XP + k];
                unsigned long long xx;
                PACK_F32X2(xx, xv, xv);
                FMA_F32X2(acc[r][0], xx, w.x, acc[r][0]);
                FMA_F32X2(acc[r][1], xx, w.y, acc[r][1]);
            }
        }
        float4 bv = make_float4(0.f, 0.f, 0.f, 0.f);
        if (BIAS) bv = *(const float4*)&bias[cg * 4];
#pragma unroll
        for (int r = 0; r < 4; r++) {
            int row = row0 + rq * 4 + r;
            if (row < NN) {
                float f0, f1, f2, f3;
                UNPACK_F32X2(f0, f1, acc[r][0]);
                UNPACK_F32X2(f2, f3, acc[r][1]);
                store4(&out[row * NC + cg * 4],
                       f0 + bv.x, f1 + bv.y, f2 + bv.z, f3 + bv.w);
            }
        }
    }
}

// ---------------- aggregate: 2 nodes per warp, 16 lanes x 4 dims per node --------
// Halves LDG instruction count per edge: one row-LDG serves two edges (lanes
// 0-15 -> node A's edge row, lanes 16-31 -> node B's). Feature buffer viewed as
// uint2 (4 halves = 8 bytes per lane).
__global__ void __launch_bounds__(256) k_gather(const uint2* __restrict__ hw,
                                                const float* __restrict__ bias,
                                                uint2* __restrict__ hout) {
    int wrp  = blockIdx.x * 8 + (threadIdx.x >> 5);
    if (wrp * 2 >= NN) return;                 // whole-warp guard (NN even)
    int lane = threadIdx.x & 31;
    int half = lane >> 4;                      // which node of the pair
    int sub  = lane & 15;                      // dim group: 4*sub .. 4*sub+3
    int node = wrp * 2 + half;

    float di = g_dinv[node];
    float self = di * di;
    uint2 sv = __ldg(&hw[node * 16 + sub]);
    float2 s0 = __half22float2(*(__half2*)&sv.x);
    float2 s1 = __half22float2(*(__half2*)&sv.y);
    float a0 = self * s0.x, a1 = self * s0.y;
    float a2 = self * s1.x, a3 = self * s1.y;

    int j   = g_rowptr[node];
    int end = g_rowptr[node + 1];

    while (__any_sync(~0u, j < end)) {
#pragma unroll
        for (int k = 0; k < 4; k++) {
            bool act = j < end;
            int jj = act ? j : 0;
            int2 e = __ldg(&g_edge[jj]);
            float w = act ? __int_as_float(e.y) : 0.f;
            uint2 u = __ldg(&hw[e.x * 16 + sub]);
            float2 g0 = __half22float2(*(__half2*)&u.x);
            float2 g1 = __half22float2(*(__half2*)&u.y);
            a0 = fmaf(w, g0.x, a0); a1 = fmaf(w, g0.y, a1);
            a2 = fmaf(w, g1.x, a2); a3 = fmaf(w, g1.y, a3);
            j++;
        }
    }

    float4 b = ((const float4*)bias)[sub];
    a0 = fmaxf(a0 + b.x, 0.f);
    a1 = fmaxf(a1 + b.y, 0.f);
    a2 = fmaxf(a2 + b.z, 0.f);
    a3 = fmaxf(a3 + b.w, 0.f);
    uint2 o;
    *(__half2*)&o.x = __floats2half2_rn(a0, a1);
    *(__half2*)&o.y = __floats2half2_rn(a2, a3);
    hout[node * 16 + sub] = o;
}

// ---------------- launch ----------------
extern "C" void kernel_launch(void* const* d_in, const int* in_sizes, int n_in,
                              void* d_out, int out_size) {
    const float* x  = (const float*)d_in[0];
    const int*   ei = (const int*)d_in[1];
    const float* W1 = (const float*)d_in[2];
    const float* b1 = (const float*)d_in[3];
    const float* W2 = (const float*)d_in[4];
    const float* b2 = (const float*)d_in[5];
    const float* Wl = (const float*)d_in[6];
    const float* bl = (const float*)d_in[7];
    float*       out = (float*)d_out;

    __half* bufh; cudaGetSymbolAddress((void**)&bufh, g_bufh);
    __half* buf2; cudaGetSymbolAddress((void**)&buf2, g_buf2);

    static cudaStream_t s2 = nullptr;
    static cudaEvent_t evFork = nullptr, evJoin = nullptr;
    if (s2 == nullptr) {
        cudaStreamCreateWithFlags(&s2, cudaStreamNonBlocking);
        cudaEventCreateWithFlags(&evFork, cudaEventDisableTiming);
        cudaEventCreateWithFlags(&evJoin, cudaEventDisableTiming);
    }

    const int TB = 256;
    int gE = (NE + TB - 1) / TB;
    const int GEMM_GRID = 296;
    const int GATHER_GRID = (NN / 2 + 7) / 8;   // 2 nodes per warp, 8 warps per block

    // fork: GEMM1 (x @ W1) fully independent of the CSR build
    cudaEventRecord(evFork, 0);
    cudaStreamWaitEvent(s2, evFork, 0);
    k_gemm<64, float, __half, false><<<GEMM_GRID, 256, 0, s2>>>(x, W1, nullptr, bufh);
    cudaEventRecord(evJoin, s2);

    // CSR build (concurrent with GEMM1); count has no predecessors
    k_count<<<gE, TB>>>(ei);
    k_scan<<<SCAN_B, 1024>>>();
    k_fill<<<gE, TB>>>(ei);

    // join, then alternate gather / GEMM
    cudaStreamWaitEvent(0, evJoin, 0);
    k_gather<<<GATHER_GRID, 256>>>((const uint2*)bufh, b1, (uint2*)buf2);
    k_gemm<64, __half, __half, false><<<GEMM_GRID, 256>>>(buf2, W2, nullptr, bufh);
    k_gather<<<GATHER_GRID, 256>>>((const uint2*)bufh, b2, (uint2*)buf2);
    k_gemm<32, __half, float, true><<<GEMM_GRID, 256>>>(buf2, Wl, bl, out);
}

// round 11
// speedup vs baseline: 1.1086x; 1.0220x over previous
#include <cuda_runtime.h>
#include <cuda_fp16.h>

#define NN 100000
#define NE 1200000
#define SCAN_B 98   // ceil(NN / 1024)

// ---------------- device scratch (no allocations allowed) ----------------
// g_cnt / g_bval are zero at module load; k_scan re-zeroes g_cnt and k_fill
// re-zeroes g_bval each call, so every graph replay starts from clean state.
__device__ int                g_cnt[NN];
__device__ float              g_dinv[NN];
__device__ int                g_rowptr[NN + 1];
__device__ int2               g_nodei[NN];         // {rowptr, dinv-as-int} for fill
__device__ int                g_rank[NE];          // within-bucket rank of each edge
__device__ int2               g_edge[NE];          // {src, norm-as-int}
__device__ unsigned long long g_bval[SCAN_B];      // packed (flag<<32 | blocksum)
__device__ __half             g_bufh[NN * 64];     // transformed features (gather operand)
__device__ __half             g_buf2[NN * 64];     // aggregated hidden state

// packed f32x2 FMA (sm_103a FFMA2; 2x fp32 FMA throughput)
#define FMA_F32X2(d, a, b, c) \
    asm("fma.rn.f32x2 %0, %1, %2, %3;" : "=l"(d) : "l"(a), "l"(b), "l"(c))
#define PACK_F32X2(out, lo, hi) \
    asm("mov.b64 %0, {%1, %2};" : "=l"(out) : "f"(lo), "f"(hi))
#define UNPACK_F32X2(lo, hi, in) \
    asm("mov.b64 {%0, %1}, %2;" : "=f"(lo), "=f"(hi) : "l"(in))

// ---------------- per-block dtype probe (first 128 values, L2-hit) ----------------
__device__ __forceinline__ int probe_is64(const int* __restrict__ raw) {
    __shared__ int s_is64;
    if (threadIdx.x < 32) {
        bool ok = true;
#pragma unroll
        for (int k = 0; k < 4; k++) {
            int idx = threadIdx.x * 4 + k;
            ok &= (raw[2 * idx + 1] == 0) && ((unsigned)raw[2 * idx] < NN);
        }
        unsigned m = __ballot_sync(~0u, ok);
        if (threadIdx.x == 0) s_is64 = (m == ~0u) ? 1 : 0;
    }
    __syncthreads();
    return s_is64;
}

__device__ __forceinline__ int edge_at(const int* raw, int idx, int is64) {
    return is64 ? (int)((const long long*)raw)[idx] : raw[idx];
}

// ---------------- count + rank (no predecessors) ----------------
__global__ void k_count(const int* __restrict__ raw) {
    int is64 = probe_is64(raw);
    int e = blockIdx.x * blockDim.x + threadIdx.x;
    if (e >= NE) return;
    int d = edge_at(raw, NE + e, is64);
    int r = 0;
    if ((unsigned)d < NN) r = atomicAdd(&g_cnt[d], 1);
    g_rank[e] = r;
}

// ---------------- single-kernel scan (98 blocks co-resident, decoupled lookback) ----
__global__ void __launch_bounds__(1024) k_scan() {
    __shared__ int wsum[32];
    __shared__ int s_boff;
    int tid = threadIdx.x;
    int lane = tid & 31, wid = tid >> 5;
    int i = blockIdx.x * 1024 + tid;
    int c = (i < NN) ? g_cnt[i] : 0;
    float dv = rsqrtf((float)c + 1.0f);
    if (i < NN) {
        g_dinv[i] = dv;
        g_cnt[i] = 0;                          // reset for next replay
    }

    int incl = c;
#pragma unroll
    for (int o = 1; o < 32; o <<= 1) {
        int t = __shfl_up_sync(~0u, incl, o);
        if (lane >= o) incl += t;
    }
    if (lane == 31) wsum[wid] = incl;
    __syncthreads();
    if (tid < 32) {
        int w = wsum[tid];
        int iw = w;
#pragma unroll
        for (int o = 1; o < 32; o <<= 1) {
            int t = __shfl_up_sync(~0u, iw, o);
            if (tid >= o) iw += t;
        }
        wsum[tid] = iw - w;                    // exclusive warp offset
        if (tid == 31)                         // publish block aggregate
            atomicExch(&g_bval[blockIdx.x], (1ull << 32) | (unsigned)iw);
    }
    __syncthreads();

    if (wid == 0) {
        int my = blockIdx.x;
        unsigned acc = 0;
        for (int base = 0; base < my; base += 32) {
            int j = base + lane;
            if (j < my) {
                unsigned long long v;
                do { v = atomicAdd(&g_bval[j], 0ull); } while ((v >> 32) == 0);
                acc += (unsigned)v;
            }
        }
#pragma unroll
        for (int o = 16; o; o >>= 1) acc += __shfl_down_sync(~0u, acc, o);
        if (lane == 0) s_boff = (int)acc;
    }
    __syncthreads();

    if (i < NN) {
        int excl = incl - c + wsum[wid] + s_boff;
        g_rowptr[i] = excl;
        g_nodei[i] = make_int2(excl, __float_as_int(dv));   // packed for fill
    }
    if (blockIdx.x == 0 && tid == 0) g_rowptr[NN] = NE;
}

// ---------------- fill CSR: atomic-free; one packed random read for dst ----------------
__global__ void k_fill(const int* __restrict__ raw) {
    int is64 = probe_is64(raw);
    if (blockIdx.x == 0 && threadIdx.x < SCAN_B) g_bval[threadIdx.x] = 0ull;
    int e = blockIdx.x * blockDim.x + threadIdx.x;
    if (e >= NE) return;
    int s = edge_at(raw, e, is64);
    int d = edge_at(raw, NE + e, is64);
    if ((unsigned)s >= NN || (unsigned)d >= NN) return;
    int2 nd = g_nodei[d];                      // {rowptr[d], dinv[d]}
    int pos = nd.x + g_rank[e];
    float norm = g_dinv[s] * __int_as_float(nd.y);
    g_edge[pos] = make_int2(s, __float_as_int(norm));
}

// ---------------- stores ----------------
__device__ __forceinline__ void store4(float* p, float a, float b, float c, float d) {
    *(float4*)p = make_float4(a, b, c, d);
}
__device__ __forceinline__ void store4(__half* p, float a, float b, float c, float d) {
    *(__half2*)p = __floats2half2_rn(a, b);
    *(__half2*)(p + 2) = __floats2half2_rn(c, d);
}

// ---------------- dense GEMM: out[N,NC] = in[N,64] @ W[64,NC] (+bias) ----------------
template <int NC, typename InT, typename OutT, bool BIAS>
__global__ void __launch_bounds__(256) k_gemm(const InT* __restrict__ in,
                                              const float* __restrict__ W,
                                              const float* __restrict__ bias,
                                              OutT* __restrict__ out) {
    constexpr int CG = NC / 4;
    constexpr int RQ = 256 / CG;
    constexpr int TM = RQ * 4;
    constexpr int XP = 65;
    __shared__ float Ws[64 * NC];
    __shared__ float Xs[TM * XP];

    for (int i = threadIdx.x; i < 64 * NC; i += 256) Ws[i] = W[i];

    int rq = threadIdx.x / CG;
    int cg = threadIdx.x % CG;
    int ntiles = (NN + TM - 1) / TM;

    for (int tile = blockIdx.x; tile < ntiles; tile += gridDim.x) {
        int row0 = tile * TM;
        int nr = min(TM, NN - row0);
        __syncthreads();
        if constexpr (sizeof(InT) == 4) {
            const float* src = (const float*)in + row0 * 64;
            for (int i = threadIdx.x; i < nr * 64; i += 256)
                Xs[(i >> 6) * XP + (i & 63)] = src[i];
        } else {
            const __half2* src = (const __half2*)((const __half*)in + row0 * 64);
            for (int i = threadIdx.x; i < nr * 32; i += 256) {
                float2 f = __half22float2(src[i]);
                int r = i >> 5, c = (i & 31) * 2;
                Xs[r * XP + c] = f.x;
                Xs[r * XP + c + 1] = f.y;
            }
        }
        __syncthreads();

        unsigned long long acc[4][2] = {};
#pragma unroll 4
        for (int k = 0; k < 64; k++) {
            ulonglong2 w = *(const ulonglong2*)&Ws[k * NC + cg * 4];
#pragma unroll
            for (int r = 0; r < 4; r++) {
                float xv = Xs[(rq * 4 + r) * XP + k];
                unsigned long long xx;
                PACK_F32X2(xx, xv, xv);
                FMA_F32X2(acc[r][0], xx, w.x, acc[r][0]);
                FMA_F32X2(acc[r][1], xx, w.y, acc[r][1]);
            }
        }
        float4 bv = make_float4(0.f, 0.f, 0.f, 0.f);
        if (BIAS) bv = *(const float4*)&bias[cg * 4];
#pragma unroll
        for (int r = 0; r < 4; r++) {
            int row = row0 + rq * 4 + r;
            if (row < NN) {
                float f0, f1, f2, f3;
                UNPACK_F32X2(f0, f1, acc[r][0]);
                UNPACK_F32X2(f2, f3, acc[r][1]);
                store4(&out[row * NC + cg * 4],
                       f0 + bv.x, f1 + bv.y, f2 + bv.z, f3 + bv.w);
            }
        }
    }
}

// ---------------- aggregate: 4 nodes per warp, 8 lanes x 8 dims per node --------
// One row-LDG (uint4 = 16B x 8 lanes = 128B row) serves FOUR edges; one edge
// LDG serves four quarters. Instructions per edge: ~0.5 LDG.
__global__ void __launch_bounds__(256) k_gather(const uint4* __restrict__ hw,
                                                const float* __restrict__ bias,
                                                uint4* __restrict__ hout) {
    int wrp  = blockIdx.x * 8 + (threadIdx.x >> 5);
    if (wrp * 4 >= NN) return;                 // NN % 4 == 0: whole warps exact
    int lane = threadIdx.x & 31;
    int sub  = lane & 7;                       // dim group: 8*sub .. 8*sub+7
    int node = wrp * 4 + (lane >> 3);

    float di = g_dinv[node];
    float self = di * di;
    uint4 sv = __ldg(&hw[node * 8 + sub]);
    float2 s0 = __half22float2(*(__half2*)&sv.x);
    float2 s1 = __half22float2(*(__half2*)&sv.y);
    float2 s2 = __half22float2(*(__half2*)&sv.z);
    float2 s3 = __half22float2(*(__half2*)&sv.w);
    float a0 = self * s0.x, a1 = self * s0.y;
    float a2 = self * s1.x, a3 = self * s1.y;
    float a4 = self * s2.x, a5 = self * s2.y;
    float a6 = self * s3.x, a7 = self * s3.y;

    int j   = g_rowptr[node];
    int end = g_rowptr[node + 1];

    while (__any_sync(~0u, j < end)) {
#pragma unroll
        for (int k = 0; k < 4; k++) {
            bool act = j < end;
            int jj = act ? j : 0;
            int2 e = __ldg(&g_edge[jj]);
            float w = act ? __int_as_float(e.y) : 0.f;
            uint4 u = __ldg(&hw[e.x * 8 + sub]);
            float2 g0 = __half22float2(*(__half2*)&u.x);
            float2 g1 = __half22float2(*(__half2*)&u.y);
            float2 g2 = __half22float2(*(__half2*)&u.z);
            float2 g3 = __half22float2(*(__half2*)&u.w);
            a0 = fmaf(w, g0.x, a0); a1 = fmaf(w, g0.y, a1);
            a2 = fmaf(w, g1.x, a2); a3 = fmaf(w, g1.y, a3);
            a4 = fmaf(w, g2.x, a4); a5 = fmaf(w, g2.y, a5);
            a6 = fmaf(w, g3.x, a6); a7 = fmaf(w, g3.y, a7);
            j++;
        }
    }

    const float4* b4 = (const float4*)bias;
    float4 bl = b4[2 * sub], bh = b4[2 * sub + 1];
    a0 = fmaxf(a0 + bl.x, 0.f);
    a1 = fmaxf(a1 + bl.y, 0.f);
    a2 = fmaxf(a2 + bl.z, 0.f);
    a3 = fmaxf(a3 + bl.w, 0.f);
    a4 = fmaxf(a4 + bh.x, 0.f);
    a5 = fmaxf(a5 + bh.y, 0.f);
    a6 = fmaxf(a6 + bh.z, 0.f);
    a7 = fmaxf(a7 + bh.w, 0.f);
    uint4 o;
    *(__half2*)&o.x = __floats2half2_rn(a0, a1);
    *(__half2*)&o.y = __floats2half2_rn(a2, a3);
    *(__half2*)&o.z = __floats2half2_rn(a4, a5);
    *(__half2*)&o.w = __floats2half2_rn(a6, a7);
    hout[node * 8 + sub] = o;
}

// ---------------- launch ----------------
extern "C" void kernel_launch(void* const* d_in, const int* in_sizes, int n_in,
                              void* d_out, int out_size) {
    const float* x  = (const float*)d_in[0];
    const int*   ei = (const int*)d_in[1];
    const float* W1 = (const float*)d_in[2];
    const float* b1 = (const float*)d_in[3];
    const float* W2 = (const float*)d_in[4];
    const float* b2 = (const float*)d_in[5];
    const float* Wl = (const float*)d_in[6];
    const float* bl = (const float*)d_in[7];
    float*       out = (float*)d_out;

    __half* bufh; cudaGetSymbolAddress((void**)&bufh, g_bufh);
    __half* buf2; cudaGetSymbolAddress((void**)&buf2, g_buf2);

    static cudaStream_t s2 = nullptr;
    static cudaEvent_t evFork = nullptr, evJoin = nullptr;
    if (s2 == nullptr) {
        cudaStreamCreateWithFlags(&s2, cudaStreamNonBlocking);
        cudaEventCreateWithFlags(&evFork, cudaEventDisableTiming);
        cudaEventCreateWithFlags(&evJoin, cudaEventDisableTiming);
    }

    const int TB = 256;
    int gE = (NE + TB - 1) / TB;
    const int GEMM_GRID = 296;
    const int GATHER_GRID = (NN / 4 + 7) / 8;   // 4 nodes per warp, 8 warps per block

    // fork: GEMM1 (x @ W1) fully independent of the CSR build
    cudaEventRecord(evFork, 0);
    cudaStreamWaitEvent(s2, evFork, 0);
    k_gemm<64, float, __half, false><<<GEMM_GRID, 256, 0, s2>>>(x, W1, nullptr, bufh);
    cudaEventRecord(evJoin, s2);

    // CSR build (concurrent with GEMM1); count has no predecessors
    k_count<<<gE, TB>>>(ei);
    k_scan<<<SCAN_B, 1024>>>();
    k_fill<<<gE, TB>>>(ei);

    // join, then alternate gather / GEMM
    cudaStreamWaitEvent(0, evJoin, 0);
    k_gather<<<GATHER_GRID, 256>>>((const uint4*)bufh, b1, (uint4*)buf2);
    k_gemm<64, __half, __half, false><<<GEMM_GRID, 256>>>(buf2, W2, nullptr, bufh);
    k_gather<<<GATHER_GRID, 256>>>((const uint4*)bufh, b2, (uint4*)buf2);
    k_gemm<32, __half, float, true><<<GEMM_GRID, 256>>>(buf2, Wl, bl, out);
}

// round 12
// speedup vs baseline: 1.1392x; 1.0276x over previous
#include <cuda_runtime.h>
#include <cuda_fp16.h>

#define NN 100000
#define NE 1200000
#define SCAN_B 98   // ceil(NN / 1024)

// ---------------- device scratch (no allocations allowed) ----------------
// g_cnt / g_bval are zero at module load; k_scan re-zeroes g_cnt and k_fill
// re-zeroes g_bval each call, so every graph replay starts from clean state.
__device__ int                g_cnt[NN];
__device__ float              g_dinv[NN];
__device__ int                g_rowptr[NN + 1];
__device__ int                g_rank[NE];          // within-bucket rank of each edge
__device__ int                g_col[NE];           // CSR column = src node (no norm!)
__device__ unsigned long long g_bval[SCAN_B];      // packed (flag<<32 | blocksum)
__device__ __half             g_bufh[NN * 64];     // dinv-scaled transformed features
__device__ __half             g_buf2[NN * 64];     // aggregated hidden state

// packed f32x2 FMA (sm_103a FFMA2; 2x fp32 FMA throughput)
#define FMA_F32X2(d, a, b, c) \
    asm("fma.rn.f32x2 %0, %1, %2, %3;" : "=l"(d) : "l"(a), "l"(b), "l"(c))
#define PACK_F32X2(out, lo, hi) \
    asm("mov.b64 %0, {%1, %2};" : "=l"(out) : "f"(lo), "f"(hi))
#define UNPACK_F32X2(lo, hi, in) \
    asm("mov.b64 {%0, %1}, %2;" : "=f"(lo), "=f"(hi) : "l"(in))

// ---------------- per-block dtype probe (first 128 values, L2-hit) ----------------
__device__ __forceinline__ int probe_is64(const int* __restrict__ raw) {
    __shared__ int s_is64;
    if (threadIdx.x < 32) {
        bool ok = true;
#pragma unroll
        for (int k = 0; k < 4; k++) {
            int idx = threadIdx.x * 4 + k;
            ok &= (raw[2 * idx + 1] == 0) && ((unsigned)raw[2 * idx] < NN);
        }
        unsigned m = __ballot_sync(~0u, ok);
        if (threadIdx.x == 0) s_is64 = (m == ~0u) ? 1 : 0;
    }
    __syncthreads();
    return s_is64;
}

__device__ __forceinline__ int edge_at(const int* raw, int idx, int is64) {
    return is64 ? (int)((const long long*)raw)[idx] : raw[idx];
}

// ---------------- count + rank (no predecessors) ----------------
__global__ void k_count(const int* __restrict__ raw) {
    int is64 = probe_is64(raw);
    int e = blockIdx.x * blockDim.x + threadIdx.x;
    if (e >= NE) return;
    int d = edge_at(raw, NE + e, is64);
    int r = 0;
    if ((unsigned)d < NN) r = atomicAdd(&g_cnt[d], 1);
    g_rank[e] = r;
}

// ---------------- single-kernel scan (98 blocks co-resident, decoupled lookback) ----
__global__ void __launch_bounds__(1024) k_scan() {
    __shared__ int wsum[32];
    __shared__ int s_boff;
    int tid = threadIdx.x;
    int lane = tid & 31, wid = tid >> 5;
    int i = blockIdx.x * 1024 + tid;
    int c = (i < NN) ? g_cnt[i] : 0;
    if (i < NN) {
        g_dinv[i] = rsqrtf((float)c + 1.0f);
        g_cnt[i] = 0;                          // reset for next replay
    }

    int incl = c;
#pragma unroll
    for (int o = 1; o < 32; o <<= 1) {
        int t = __shfl_up_sync(~0u, incl, o);
        if (lane >= o) incl += t;
    }
    if (lane == 31) wsum[wid] = incl;
    __syncthreads();
    if (tid < 32) {
        int w = wsum[tid];
        int iw = w;
#pragma unroll
        for (int o = 1; o < 32; o <<= 1) {
            int t = __shfl_up_sync(~0u, iw, o);
            if (tid >= o) iw += t;
        }
        wsum[tid] = iw - w;                    // exclusive warp offset
        if (tid == 31)                         // publish block aggregate
            atomicExch(&g_bval[blockIdx.x], (1ull << 32) | (unsigned)iw);
    }
    __syncthreads();

    if (wid == 0) {
        int my = blockIdx.x;
        unsigned acc = 0;
        for (int base = 0; base < my; base += 32) {
            int j = base + lane;
            if (j < my) {
                unsigned long long v;
                do { v = atomicAdd(&g_bval[j], 0ull); } while ((v >> 32) == 0);
                acc += (unsigned)v;
            }
        }
#pragma unroll
        for (int o = 16; o; o >>= 1) acc += __shfl_down_sync(~0u, acc, o);
        if (lane == 0) s_boff = (int)acc;
    }
    __syncthreads();

    if (i < NN) g_rowptr[i] = incl - c + wsum[wid] + s_boff;
    if (blockIdx.x == 0 && tid == 0) g_rowptr[NN] = NE;
}

// ---------------- fill CSR: bare src column, atomic-free, no norm ----------------
__global__ void k_fill(const int* __restrict__ raw) {
    int is64 = probe_is64(raw);
    if (blockIdx.x == 0 && threadIdx.x < SCAN_B) g_bval[threadIdx.x] = 0ull;
    int e = blockIdx.x * blockDim.x + threadIdx.x;
    if (e >= NE) return;
    int s = edge_at(raw, e, is64);
    int d = edge_at(raw, NE + e, is64);
    if ((unsigned)s >= NN || (unsigned)d >= NN) return;
    g_col[g_rowptr[d] + g_rank[e]] = s;
}

// ---------------- stores ----------------
__device__ __forceinline__ void store4(float* p, float a, float b, float c, float d) {
    *(float4*)p = make_float4(a, b, c, d);
}
__device__ __forceinline__ void store4(__half* p, float a, float b, float c, float d) {
    *(__half2*)p = __floats2half2_rn(a, b);
    *(__half2*)(p + 2) = __floats2half2_rn(c, d);
}

// ---------------- dense GEMM: out[N,NC] = (dinv[i]·) in[N,64] @ W[64,NC] (+bias) ----
template <int NC, typename InT, typename OutT, bool BIAS, bool SCALE>
__global__ void __launch_bounds__(256) k_gemm(const InT* __restrict__ in,
                                              const float* __restrict__ W,
                                              const float* __restrict__ bias,
                                              OutT* __restrict__ out) {
    constexpr int CG = NC / 4;
    constexpr int RQ = 256 / CG;
    constexpr int TM = RQ * 4;
    constexpr int XP = 65;
    __shared__ float Ws[64 * NC];
    __shared__ float Xs[TM * XP];

    for (int i = threadIdx.x; i < 64 * NC; i += 256) Ws[i] = W[i];

    int rq = threadIdx.x / CG;
    int cg = threadIdx.x % CG;
    int ntiles = (NN + TM - 1) / TM;

    for (int tile = blockIdx.x; tile < ntiles; tile += gridDim.x) {
        int row0 = tile * TM;
        int nr = min(TM, NN - row0);
        __syncthreads();
        if constexpr (sizeof(InT) == 4) {
            const float* src = (const float*)in + row0 * 64;
            for (int i = threadIdx.x; i < nr * 64; i += 256)
                Xs[(i >> 6) * XP + (i & 63)] = src[i];
        } else {
            const __half2* src = (const __half2*)((const __half*)in + row0 * 64);
            for (int i = threadIdx.x; i < nr * 32; i += 256) {
                float2 f = __half22float2(src[i]);
                int r = i >> 5, c = (i & 31) * 2;
                Xs[r * XP + c] = f.x;
                Xs[r * XP + c + 1] = f.y;
            }
        }
        __syncthreads();

        unsigned long long acc[4][2] = {};
#pragma unroll 4
        for (int k = 0; k < 64; k++) {
            ulonglong2 w = *(const ulonglong2*)&Ws[k * NC + cg * 4];
#pragma unroll
            for (int r = 0; r < 4; r++) {
                float xv = Xs[(rq * 4 + r) * XP + k];
                unsigned long long xx;
                PACK_F32X2(xx, xv, xv);
                FMA_F32X2(acc[r][0], xx, w.x, acc[r][0]);
                FMA_F32X2(acc[r][1], xx, w.y, acc[r][1]);
            }
        }
        float4 bv = make_float4(0.f, 0.f, 0.f, 0.f);
        if (BIAS) bv = *(const float4*)&bias[cg * 4];
#pragma unroll
        for (int r = 0; r < 4; r++) {
            int row = row0 + rq * 4 + r;
            if (row < NN) {
                float f0, f1, f2, f3;
                UNPACK_F32X2(f0, f1, acc[r][0]);
                UNPACK_F32X2(f2, f3, acc[r][1]);
                if (SCALE) {
                    float dv = __ldg(&g_dinv[row]);
                    f0 *= dv; f1 *= dv; f2 *= dv; f3 *= dv;
                }
                store4(&out[row * NC + cg * 4],
                       f0 + bv.x, f1 + bv.y, f2 + bv.z, f3 + bv.w);
            }
        }
    }
}

// ---------------- aggregate: 4 nodes per warp, 8 lanes x 8 dims per node --------
// Edge stream is bare src indices (4B). out[d] = relu(dinv[d]*(sum hs[src] + hs[d]) + b)
__global__ void __launch_bounds__(256) k_gather(const uint4* __restrict__ hw,
                                                const float* __restrict__ bias,
                                                uint4* __restrict__ hout) {
    int wrp  = blockIdx.x * 8 + (threadIdx.x >> 5);
    if (wrp * 4 >= NN) return;                 // NN % 4 == 0: whole warps exact
    int lane = threadIdx.x & 31;
    int sub  = lane & 7;                       // dim group: 8*sub .. 8*sub+7
    int node = wrp * 4 + (lane >> 3);

    uint4 sv = __ldg(&hw[node * 8 + sub]);     // self term hs[d]
    float2 s0 = __half22float2(*(__half2*)&sv.x);
    float2 s1 = __half22float2(*(__half2*)&sv.y);
    float2 s2 = __half22float2(*(__half2*)&sv.z);
    float2 s3 = __half22float2(*(__half2*)&sv.w);
    float a0 = s0.x, a1 = s0.y, a2 = s1.x, a3 = s1.y;
    float a4 = s2.x, a5 = s2.y, a6 = s3.x, a7 = s3.y;

    int j   = g_rowptr[node];
    int end = g_rowptr[node + 1];

    while (__any_sync(~0u, j < end)) {
#pragma unroll
        for (int k = 0; k < 4; k++) {
            bool act = j < end;
            int jj = act ? j : 0;
            int c = __ldg(&g_col[jj]);
            float m = act ? 1.0f : 0.0f;
            uint4 u = __ldg(&hw[c * 8 + sub]);
            float2 g0 = __half22float2(*(__half2*)&u.x);
            float2 g1 = __half22float2(*(__half2*)&u.y);
            float2 g2 = __half22float2(*(__half2*)&u.z);
            float2 g3 = __half22float2(*(__half2*)&u.w);
            a0 = fmaf(m, g0.x, a0); a1 = fmaf(m, g0.y, a1);
            a2 = fmaf(m, g1.x, a2); a3 = fmaf(m, g1.y, a3);
            a4 = fmaf(m, g2.x, a4); a5 = fmaf(m, g2.y, a5);
            a6 = fmaf(m, g3.x, a6); a7 = fmaf(m, g3.y, a7);
            j++;
        }
    }

    float dv = __ldg(&g_dinv[node]);
    const float4* b4 = (const float4*)bias;
    float4 bl = b4[2 * sub], bh = b4[2 * sub + 1];
    a0 = fmaxf(fmaf(a0, dv, bl.x), 0.f);
    a1 = fmaxf(fmaf(a1, dv, bl.y), 0.f);
    a2 = fmaxf(fmaf(a2, dv, bl.z), 0.f);
    a3 = fmaxf(fmaf(a3, dv, bl.w), 0.f);
    a4 = fmaxf(fmaf(a4, dv, bh.x), 0.f);
    a5 = fmaxf(fmaf(a5, dv, bh.y), 0.f);
    a6 = fmaxf(fmaf(a6, dv, bh.z), 0.f);
    a7 = fmaxf(fmaf(a7, dv, bh.w), 0.f);
    uint4 o;
    *(__half2*)&o.x = __floats2half2_rn(a0, a1);
    *(__half2*)&o.y = __floats2half2_rn(a2, a3);
    *(__half2*)&o.z = __floats2half2_rn(a4, a5);
    *(__half2*)&o.w = __floats2half2_rn(a6, a7);
    hout[node * 8 + sub] = o;
}

// ---------------- launch ----------------
extern "C" void kernel_launch(void* const* d_in, const int* in_sizes, int n_in,
                              void* d_out, int out_size) {
    const float* x  = (const float*)d_in[0];
    const int*   ei = (const int*)d_in[1];
    const float* W1 = (const float*)d_in[2];
    const float* b1 = (const float*)d_in[3];
    const float* W2 = (const float*)d_in[4];
    const float* b2 = (const float*)d_in[5];
    const float* Wl = (const float*)d_in[6];
    const float* bl = (const float*)d_in[7];
    float*       out = (float*)d_out;

    __half* bufh; cudaGetSymbolAddress((void**)&bufh, g_bufh);
    __half* buf2; cudaGetSymbolAddress((void**)&buf2, g_buf2);

    static cudaStream_t s2 = nullptr;
    static cudaEvent_t evS = nullptr, evJ = nullptr;
    if (s2 == nullptr) {
        cudaStreamCreateWithFlags(&s2, cudaStreamNonBlocking);
        cudaEventCreateWithFlags(&evS, cudaEventDisableTiming);
        cudaEventCreateWithFlags(&evJ, cudaEventDisableTiming);
    }

    const int TB = 256;
    int gE = (NE + TB - 1) / TB;
    const int GEMM_GRID = 296;
    const int GATHER_GRID = (NN / 4 + 7) / 8;   // 4 nodes per warp, 8 warps per block

    // CSR build; gemm1 needs dinv (scan), so fork it after scan, overlapping fill
    k_count<<<gE, TB>>>(ei);
    k_scan<<<SCAN_B, 1024>>>();
    cudaEventRecord(evS, 0);
    cudaStreamWaitEvent(s2, evS, 0);
    k_gemm<64, float, __half, false, true><<<GEMM_GRID, 256, 0, s2>>>(x, W1, nullptr, bufh);
    cudaEventRecord(evJ, s2);
    k_fill<<<gE, TB>>>(ei);

    // join, then alternate gather / GEMM (gemm2 scales its output by dinv)
    cudaStreamWaitEvent(0, evJ, 0);
    k_gather<<<GATHER_GRID, 256>>>((const uint4*)bufh, b1, (uint4*)buf2);
    k_gemm<64, __half, __half, false, true><<<GEMM_GRID, 256>>>(buf2, W2, nullptr, bufh);
    k_gather<<<GATHER_GRID, 256>>>((const uint4*)bufh, b2, (uint4*)buf2);
    k_gemm<32, __half, float, true, false><<<GEMM_GRID, 256>>>(buf2, Wl, bl, out);
}

// round 14
// speedup vs baseline: 1.3632x; 1.1966x over previous
#include <cuda_runtime.h>
#include <cuda_fp16.h>
#include <cstdint>

#define NN 100000
#define NE 1200000
#define SCAN_B 98   // ceil(NN / 1024)

// ---------------- device scratch (no allocations allowed) ----------------
__device__ int                g_cnt[NN];
__device__ float              g_dinv[NN];
__device__ int                g_rowptr[NN + 1];
__device__ int                g_rank[NE];
__device__ int                g_col[NE];
__device__ unsigned long long g_bval[SCAN_B];
__device__ __half             g_bufh[NN * 64];
__device__ __half             g_buf2[NN * 64];

// packed f32x2 FMA (sm_103a FFMA2)
#define FMA_F32X2(d, a, b, c) \
    asm("fma.rn.f32x2 %0, %1, %2, %3;" : "=l"(d) : "l"(a), "l"(b), "l"(c))
#define PACK_F32X2(out, lo, hi) \
    asm("mov.b64 %0, {%1, %2};" : "=l"(out) : "f"(lo), "f"(hi))
#define UNPACK_F32X2(lo, hi, in) \
    asm("mov.b64 {%0, %1}, %2;" : "=f"(lo), "=f"(hi) : "l"(in))

// HMMA m16n8k16 row.col f32 accumulate
#define MMA_16816(c0, c1, c2, c3, a0, a1, a2, a3, b0, b1) \
    asm volatile("mma.sync.aligned.m16n8k16.row.col.f32.f16.f16.f32 " \
        "{%0,%1,%2,%3}, {%4,%5,%6,%7}, {%8,%9}, {%0,%1,%2,%3};" \
        : "+f"(c0), "+f"(c1), "+f"(c2), "+f"(c3) \
        : "r"(a0), "r"(a1), "r"(a2), "r"(a3), "r"(b0), "r"(b1))

// ---------------- per-block dtype probe ----------------
__device__ __forceinline__ int probe_is64(const int* __restrict__ raw) {
    __shared__ int s_is64;
    if (threadIdx.x < 32) {
        bool ok = true;
#pragma unroll
        for (int k = 0; k < 4; k++) {
            int idx = threadIdx.x * 4 + k;
            ok &= (raw[2 * idx + 1] == 0) && ((unsigned)raw[2 * idx] < NN);
        }
        unsigned m = __ballot_sync(~0u, ok);
        if (threadIdx.x == 0) s_is64 = (m == ~0u) ? 1 : 0;
    }
    __syncthreads();
    return s_is64;
}
__device__ __forceinline__ int edge_at(const int* raw, int idx, int is64) {
    return is64 ? (int)((const long long*)raw)[idx] : raw[idx];
}

// ---------------- count + rank ----------------
__global__ void k_count(const int* __restrict__ raw) {
    int is64 = probe_is64(raw);
    int e = blockIdx.x * blockDim.x + threadIdx.x;
    if (e >= NE) return;
    int d = edge_at(raw, NE + e, is64);
    int r = 0;
    if ((unsigned)d < NN) r = atomicAdd(&g_cnt[d], 1);
    g_rank[e] = r;
}

// ---------------- single-kernel scan ----------------
__global__ void __launch_bounds__(1024) k_scan() {
    __shared__ int wsum[32];
    __shared__ int s_boff;
    int tid = threadIdx.x;
    int lane = tid & 31, wid = tid >> 5;
    int i = blockIdx.x * 1024 + tid;
    int c = (i < NN) ? g_cnt[i] : 0;
    if (i < NN) {
        g_dinv[i] = rsqrtf((float)c + 1.0f);
        g_cnt[i] = 0;
    }
    int incl = c;
#pragma unroll
    for (int o = 1; o < 32; o <<= 1) {
        int t = __shfl_up_sync(~0u, incl, o);
        if (lane >= o) incl += t;
    }
    if (lane == 31) wsum[wid] = incl;
    __syncthreads();
    if (tid < 32) {
        int w = wsum[tid];
        int iw = w;
#pragma unroll
        for (int o = 1; o < 32; o <<= 1) {
            int t = __shfl_up_sync(~0u, iw, o);
            if (tid >= o) iw += t;
        }
        wsum[tid] = iw - w;
        if (tid == 31)
            atomicExch(&g_bval[blockIdx.x], (1ull << 32) | (unsigned)iw);
    }
    __syncthreads();
    if (wid == 0) {
        int my = blockIdx.x;
        unsigned acc = 0;
        for (int base = 0; base < my; base += 32) {
            int j = base + lane;
            if (j < my) {
                unsigned long long v;
                do { v = atomicAdd(&g_bval[j], 0ull); } while ((v >> 32) == 0);
                acc += (unsigned)v;
            }
        }
#pragma unroll
        for (int o = 16; o; o >>= 1) acc += __shfl_down_sync(~0u, acc, o);
        if (lane == 0) s_boff = (int)acc;
    }
    __syncthreads();
    if (i < NN) g_rowptr[i] = incl - c + wsum[wid] + s_boff;
    if (blockIdx.x == 0 && tid == 0) g_rowptr[NN] = NE;
}

// ---------------- fill CSR ----------------
__global__ void k_fill(const int* __restrict__ raw) {
    int is64 = probe_is64(raw);
    if (blockIdx.x == 0 && threadIdx.x < SCAN_B) g_bval[threadIdx.x] = 0ull;
    int e = blockIdx.x * blockDim.x + threadIdx.x;
    if (e >= NE) return;
    int s = edge_at(raw, e, is64);
    int d = edge_at(raw, NE + e, is64);
    if ((unsigned)s >= NN || (unsigned)d >= NN) return;
    g_col[g_rowptr[d] + g_rank[e]] = s;
}

// ---------------- FFMA2 GEMM (gemm1: fp32 in, dinv-scaled fp16 out) ----------
__global__ void __launch_bounds__(256) k_gemm1(const float* __restrict__ in,
                                               const float* __restrict__ W,
                                               __half* __restrict__ out) {
    constexpr int TM = 64, XP = 65;
    __shared__ float Ws[64 * 64];
    __shared__ float Xs[TM * XP];
    for (int i = threadIdx.x; i < 64 * 64; i += 256) Ws[i] = W[i];
    int rq = threadIdx.x / 16;
    int cg = threadIdx.x % 16;
    int ntiles = (NN + TM - 1) / TM;
    for (int tile = blockIdx.x; tile < ntiles; tile += gridDim.x) {
        int row0 = tile * TM;
        int nr = min(TM, NN - row0);
        __syncthreads();
        for (int i = threadIdx.x; i < nr * 64; i += 256)
            Xs[(i >> 6) * XP + (i & 63)] = in[row0 * 64 + i];
        __syncthreads();
        unsigned long long acc[4][2] = {};
#pragma unroll 4
        for (int k = 0; k < 64; k++) {
            ulonglong2 w = *(const ulonglong2*)&Ws[k * 64 + cg * 4];
#pragma unroll
            for (int r = 0; r < 4; r++) {
                float xv = Xs[(rq * 4 + r) * XP + k];
                unsigned long long xx;
                PACK_F32X2(xx, xv, xv);
                FMA_F32X2(acc[r][0], xx, w.x, acc[r][0]);
                FMA_F32X2(acc[r][1], xx, w.y, acc[r][1]);
            }
        }
#pragma unroll
        for (int r = 0; r < 4; r++) {
            int row = row0 + rq * 4 + r;
            if (row < NN) {
                float f0, f1, f2, f3;
                UNPACK_F32X2(f0, f1, acc[r][0]);
                UNPACK_F32X2(f2, f3, acc[r][1]);
                float dv = __ldg(&g_dinv[row]);
                __half* p = &out[row * 64 + cg * 4];
                *(__half2*)p = __floats2half2_rn(f0 * dv, f1 * dv);
                *(__half2*)(p + 2) = __floats2half2_rn(f2 * dv, f3 * dv);
            }
        }
    }
}

// ---------------- HMMA GEMM: out[N,NC] = X[N,64]fp16 @ W[64,NC] ----------------
// 8 warps x 16-row tiles = 128 rows/block. B fragments (m16n8k16 row.col
// layout) precomputed in SMEM; fp32 accumulate; fused dinv-scale / bias.
template <int NC, typename OutT, bool BIAS, bool SCALE>
__global__ void __launch_bounds__(256) k_gemm_mma(const __half* __restrict__ in,
                                                  const float* __restrict__ W,
                                                  const float* __restrict__ bias,
                                                  OutT* __restrict__ out) {
    constexpr int NT = NC / 8;                 // n-tiles (8 or 4)
    constexpr int XS = 36;                     // row stride in u32 (64 halves + pad)
    __shared__ uint32_t Bf[4][NT][32][2];      // [ktile][ntile][lane][reg]
    __shared__ uint32_t Xs[128 * XS];

    int tid = threadIdx.x;
    int wid = tid >> 5, lane = tid & 31;
    int grp = lane >> 2;                       // 0..7
    int q   = lane & 3;                        // 0..3

    // Precompute B fragments: b_reg holds halves (k0, k0+1) at column n.
    for (int i = tid; i < 4 * NT * 32 * 2; i += 256) {
        int reg = i & 1;
        int ln  = (i >> 1) & 31;
        int nt  = (i >> 6) % NT;
        int kt  = (i >> 6) / NT;
        int k0 = kt * 16 + (ln & 3) * 2 + reg * 8;
        int n  = nt * 8 + (ln >> 2);
        __half2 h = __floats2half2_rn(W[k0 * NC + n], W[(k0 + 1) * NC + n]);
        Bf[kt][nt][ln][reg] = *(uint32_t*)&h;
    }

    const uint32_t* in32 = (const uint32_t*)in;
    int ntiles = (NN + 127) / 128;
    for (int tile = blockIdx.x; tile < ntiles; tile += gridDim.x) {
        int row0 = tile * 128;
        __syncthreads();
        for (int i = tid; i < 128 * 32; i += 256) {
            int r = i >> 5, c = i & 31;
            uint32_t v = 0;
            if (row0 + r < NN) v = in32[(size_t)(row0 + r) * 32 + c];
            Xs[r * XS + c] = v;
        }
        __syncthreads();

        int rb = wid * 16;                     // warp's rows within tile
        float acc[NT][4];
#pragma unroll
        for (int nt = 0; nt < NT; nt++)
#pragma unroll
            for (int c = 0; c < 4; c++) acc[nt][c] = 0.f;

#pragma unroll
        for (int kt = 0; kt < 4; kt++) {
            // A fragments: a0 (row g, k 2q..2q+1), a1 (row g+8), a2 (k+8), a3
            uint32_t a0 = Xs[(rb + grp) * XS + kt * 8 + q];
            uint32_t a1 = Xs[(rb + grp + 8) * XS + kt * 8 + q];
            uint32_t a2 = Xs[(rb + grp) * XS + kt * 8 + 4 + q];
            uint32_t a3 = Xs[(rb + grp + 8) * XS + kt * 8 + 4 + q];
#pragma unroll
            for (int nt = 0; nt < NT; nt++) {
                uint32_t b0 = Bf[kt][nt][lane][0];
                uint32_t b1 = Bf[kt][nt][lane][1];
                MMA_16816(acc[nt][0], acc[nt][1], acc[nt][2], acc[nt][3],
                          a0, a1, a2, a3, b0, b1);
            }
        }

        // Epilogue: c0,c1 -> (row rb+grp, col nt*8+2q..+1); c2,c3 -> row+8
        int r0 = row0 + rb + grp;
        int r1 = r0 + 8;
        if constexpr (NC == 64) {
            float dv0 = (r0 < NN) ? __ldg(&g_dinv[r0]) : 0.f;
            float dv1 = (r1 < NN) ? __ldg(&g_dinv[r1]) : 0.f;
            if (!SCALE) { dv0 = 1.f; dv1 = 1.f; }
#pragma unroll
            for (int nt = 0; nt < NT; nt++) {
                int col = nt * 8 + q * 2;
                if (r0 < NN)
                    *(__half2*)((__half*)out + (size_t)r0 * NC + col) =
                        __floats2half2_rn(acc[nt][0] * dv0, acc[nt][1] * dv0);
                if (r1 < NN)
                    *(__half2*)((__half*)out + (size_t)r1 * NC + col) =
                        __floats2half2_rn(acc[nt][2] * dv1, acc[nt][3] * dv1);
            }
        } else {
#pragma unroll
            for (int nt = 0; nt < NT; nt++) {
                int col = nt * 8 + q * 2;
                float b0v = 0.f, b1v = 0.f;
                if (BIAS) { b0v = __ldg(&bias[col]); b1v = __ldg(&bias[col + 1]); }
                if (r0 < NN)
                    *(float2*)((float*)out + (size_t)r0 * NC + col) =
                        make_float2(acc[nt][0] + b0v, acc[nt][1] + b1v);
                if (r1 < NN)
                    *(float2*)((float*)out + (size_t)r1 * NC + col) =
                        make_float2(acc[nt][2] + b0v, acc[nt][3] + b1v);
            }
        }
    }
}

// ---------------- gather: 4 nodes/warp, 8 lanes x 8 dims ----------------
__global__ void __launch_bounds__(256) k_gather(const uint4* __restrict__ hw,
                                                const float* __restrict__ bias,
                                                uint4* __restrict__ hout) {
    int wrp  = blockIdx.x * 8 + (threadIdx.x >> 5);
    if (wrp * 4 >= NN) return;
    int lane = threadIdx.x & 31;
    int sub  = lane & 7;
    int node = wrp * 4 + (lane >> 3);

    uint4 sv = __ldg(&hw[node * 8 + sub]);
    float2 s0 = __half22float2(*(__half2*)&sv.x);
    float2 s1 = __half22float2(*(__half2*)&sv.y);
    float2 s2 = __half22float2(*(__half2*)&sv.z);
    float2 s3 = __half22float2(*(__half2*)&sv.w);
    float a0 = s0.x, a1 = s0.y, a2 = s1.x, a3 = s1.y;
    float a4 = s2.x, a5 = s2.y, a6 = s3.x, a7 = s3.y;

    int j   = g_rowptr[node];
    int end = g_rowptr[node + 1];
    while (__any_sync(~0u, j < end)) {
#pragma unroll
        for (int k = 0; k < 4; k++) {
            bool act = j < end;
            int jj = act ? j : 0;
            int c = __ldg(&g_col[jj]);
            float m = act ? 1.0f : 0.0f;
            uint4 u = __ldg(&hw[c * 8 + sub]);
            float2 g0 = __half22float2(*(__half2*)&u.x);
            float2 g1 = __half22float2(*(__half2*)&u.y);
            float2 g2 = __half22float2(*(__half2*)&u.z);
            float2 g3 = __half22float2(*(__half2*)&u.w);
            a0 = fmaf(m, g0.x, a0); a1 = fmaf(m, g0.y, a1);
            a2 = fmaf(m, g1.x, a2); a3 = fmaf(m, g1.y, a3);
            a4 = fmaf(m, g2.x, a4); a5 = fmaf(m, g2.y, a5);
            a6 = fmaf(m, g3.x, a6); a7 = fmaf(m, g3.y, a7);
            j++;
        }
    }

    float dv = __ldg(&g_dinv[node]);
    const float4* b4 = (const float4*)bias;
    float4 bl = b4[2 * sub], bh = b4[2 * sub + 1];
    a0 = fmaxf(fmaf(a0, dv, bl.x), 0.f);
    a1 = fmaxf(fmaf(a1, dv, bl.y), 0.f);
    a2 = fmaxf(fmaf(a2, dv, bl.z), 0.f);
    a3 = fmaxf(fmaf(a3, dv, bl.w), 0.f);
    a4 = fmaxf(fmaf(a4, dv, bh.x), 0.f);
    a5 = fmaxf(fmaf(a5, dv, bh.y), 0.f);
    a6 = fmaxf(fmaf(a6, dv, bh.z), 0.f);
    a7 = fmaxf(fmaf(a7, dv, bh.w), 0.f);
    uint4 o;
    *(__half2*)&o.x = __floats2half2_rn(a0, a1);
    *(__half2*)&o.y = __floats2half2_rn(a2, a3);
    *(__half2*)&o.z = __floats2half2_rn(a4, a5);
    *(__half2*)&o.w = __floats2half2_rn(a6, a7);
    hout[node * 8 + sub] = o;
}

// ---------------- launch ----------------
extern "C" void kernel_launch(void* const* d_in, const int* in_sizes, int n_in,
                              void* d_out, int out_size) {
    const float* x  = (const float*)d_in[0];
    const int*   ei = (const int*)d_in[1];
    const float* W1 = (const float*)d_in[2];
    const float* b1 = (const float*)d_in[3];
    const float* W2 = (const float*)d_in[4];
    const float* b2 = (const float*)d_in[5];
    const float* Wl = (const float*)d_in[6];
    const float* bl = (const float*)d_in[7];
    float*       out = (float*)d_out;

    __half* bufh; cudaGetSymbolAddress((void**)&bufh, g_bufh);
    __half* buf2; cudaGetSymbolAddress((void**)&buf2, g_buf2);

    static cudaStream_t s2 = nullptr;
    static cudaEvent_t evS = nullptr, evJ = nullptr;
    if (s2 == nullptr) {
        cudaStreamCreateWithFlags(&s2, cudaStreamNonBlocking);
        cudaEventCreateWithFlags(&evS, cudaEventDisableTiming);
        cudaEventCreateWithFlags(&evJ, cudaEventDisableTiming);
    }

    const int TB = 256;
    int gE = (NE + TB - 1) / TB;
    const int GATHER_GRID = (NN / 4 + 7) / 8;
    const int MMA_GRID = 296;

    // CSR build; gemm1 needs dinv -> fork after scan, overlapping fill
    k_count<<<gE, TB>>>(ei);
    k_scan<<<SCAN_B, 1024>>>();
    cudaEventRecord(evS, 0);
    cudaStreamWaitEvent(s2, evS, 0);
    k_gemm1<<<296, 256, 0, s2>>>(x, W1, bufh);
    cudaEventRecord(evJ, s2);
    k_fill<<<gE, TB>>>(ei);

    // join, then alternate gather / HMMA GEMM
    cudaStreamWaitEvent(0, evJ, 0);
    k_gather<<<GATHER_GRID, 256>>>((const uint4*)bufh, b1, (uint4*)buf2);
    k_gemm_mma<64, __half, false, true><<<MMA_GRID, 256>>>(buf2, W2, nullptr, bufh);
    k_gather<<<GATHER_GRID, 256>>>((const uint4*)bufh, b2, (uint4*)buf2);
    k_gemm_mma<32, float, true, false><<<MMA_GRID, 256>>>(buf2, Wl, bl, out);
}

// round 15
// speedup vs baseline: 1.6342x; 1.1988x over previous
#include <cuda_runtime.h>
#include <cuda_fp16.h>
#include <cstdint>

#define NN 100000
#define NE 1200000
#define SCAN_B 98   // ceil(NN / 1024)

// ---------------- device scratch (no allocations allowed) ----------------
__device__ int                g_cnt[NN];
__device__ float              g_dinv[NN];
__device__ int                g_rowptr[NN + 1];
__device__ unsigned short     g_rank16[NE];
__device__ int                g_col[NE];
__device__ unsigned long long g_bval[SCAN_B];
__device__ __half             g_bufh[NN * 64];
__device__ __half             g_buf2[NN * 64];

// HMMA m16n8k16 row.col f32 accumulate
#define MMA_16816(c0, c1, c2, c3, a0, a1, a2, a3, b0, b1) \
    asm volatile("mma.sync.aligned.m16n8k16.row.col.f32.f16.f16.f32 " \
        "{%0,%1,%2,%3}, {%4,%5,%6,%7}, {%8,%9}, {%0,%1,%2,%3};" \
        : "+f"(c0), "+f"(c1), "+f"(c2), "+f"(c3) \
        : "r"(a0), "r"(a1), "r"(a2), "r"(a3), "r"(b0), "r"(b1))

// ---------------- per-block dtype probe ----------------
__device__ __forceinline__ int probe_is64(const int* __restrict__ raw) {
    __shared__ int s_is64;
    if (threadIdx.x < 32) {
        bool ok = true;
#pragma unroll
        for (int k = 0; k < 4; k++) {
            int idx = threadIdx.x * 4 + k;
            ok &= (raw[2 * idx + 1] == 0) && ((unsigned)raw[2 * idx] < NN);
        }
        unsigned m = __ballot_sync(~0u, ok);
        if (threadIdx.x == 0) s_is64 = (m == ~0u) ? 1 : 0;
    }
    __syncthreads();
    return s_is64;
}

// load edge pair [2*e2, 2*e2+1] from stream starting at word index base
__device__ __forceinline__ int2 edge_pair(const int* __restrict__ raw,
                                          long long base, int e2, int is64) {
    if (is64) {
        longlong2 v = __ldg((const longlong2*)((const long long*)raw + base + 2 * e2));
        return make_int2((int)v.x, (int)v.y);
    }
    return __ldg((const int2*)(raw + base + 2 * e2));
}

// ---------------- count + rank: 2 edges per thread ----------------
__global__ void k_count(const int* __restrict__ raw) {
    int is64 = probe_is64(raw);
    int e2 = blockIdx.x * blockDim.x + threadIdx.x;
    if (e2 >= NE / 2) return;
    int2 d = edge_pair(raw, NE, e2, is64);
    unsigned r0 = 0, r1 = 0;
    if ((unsigned)d.x < NN) r0 = (unsigned)atomicAdd(&g_cnt[d.x], 1);
    if ((unsigned)d.y < NN) r1 = (unsigned)atomicAdd(&g_cnt[d.y], 1);
    ((unsigned*)g_rank16)[e2] = (r0 & 0xFFFFu) | (r1 << 16);
}

// ---------------- single-kernel scan (decoupled lookback) ----------------
__global__ void __launch_bounds__(1024) k_scan() {
    __shared__ int wsum[32];
    __shared__ int s_boff;
    int tid = threadIdx.x;
    int lane = tid & 31, wid = tid >> 5;
    int i = blockIdx.x * 1024 + tid;
    int c = (i < NN) ? g_cnt[i] : 0;
    if (i < NN) {
        g_dinv[i] = rsqrtf((float)c + 1.0f);
        g_cnt[i] = 0;
    }
    int incl = c;
#pragma unroll
    for (int o = 1; o < 32; o <<= 1) {
        int t = __shfl_up_sync(~0u, incl, o);
        if (lane >= o) incl += t;
    }
    if (lane == 31) wsum[wid] = incl;
    __syncthreads();
    if (tid < 32) {
        int w = wsum[tid];
        int iw = w;
#pragma unroll
        for (int o = 1; o < 32; o <<= 1) {
            int t = __shfl_up_sync(~0u, iw, o);
            if (tid >= o) iw += t;
        }
        wsum[tid] = iw - w;
        if (tid == 31)
            atomicExch(&g_bval[blockIdx.x], (1ull << 32) | (unsigned)iw);
    }
    __syncthreads();
    if (wid == 0) {
        int my = blockIdx.x;
        unsigned acc = 0;
        for (int base = 0; base < my; base += 32) {
            int j = base + lane;
            if (j < my) {
                unsigned long long v;
                do { v = atomicAdd(&g_bval[j], 0ull); } while ((v >> 32) == 0);
                acc += (unsigned)v;
            }
        }
#pragma unroll
        for (int o = 16; o; o >>= 1) acc += __shfl_down_sync(~0u, acc, o);
        if (lane == 0) s_boff = (int)acc;
    }
    __syncthreads();
    if (i < NN) g_rowptr[i] = incl - c + wsum[wid] + s_boff;
    if (blockIdx.x == 0 && tid == 0) g_rowptr[NN] = NE;
}

// ---------------- fill CSR: 2 edges per thread, atomic-free ----------------
__global__ void k_fill(const int* __restrict__ raw) {
    int is64 = probe_is64(raw);
    if (blockIdx.x == 0 && threadIdx.x < SCAN_B) g_bval[threadIdx.x] = 0ull;
    int e2 = blockIdx.x * blockDim.x + threadIdx.x;
    if (e2 >= NE / 2) return;
    int2 s = edge_pair(raw, 0, e2, is64);
    int2 d = edge_pair(raw, NE, e2, is64);
    unsigned rr = ((const unsigned*)g_rank16)[e2];
    if ((unsigned)s.x < NN && (unsigned)d.x < NN)
        g_col[g_rowptr[d.x] + (int)(rr & 0xFFFFu)] = s.x;
    if ((unsigned)s.y < NN && (unsigned)d.y < NN)
        g_col[g_rowptr[d.y] + (int)(rr >> 16)] = s.y;
}

// ---------------- HMMA GEMM: out[N,NC] = X[N,64] @ W[64,NC] ----------------
// 8 warps x 16-row tiles = 128 rows/block. B fragments (m16n8k16 row.col
// layout) precomputed in SMEM; fp32 accumulate; fused dinv-scale / bias.
// InT = float (converted to fp16 in staging) or __half.
template <int NC, typename InT, typename OutT, bool BIAS, bool SCALE>
__global__ void __launch_bounds__(256) k_gemm_mma(const InT* __restrict__ in,
                                                  const float* __restrict__ W,
                                                  const float* __restrict__ bias,
                                                  OutT* __restrict__ out) {
    constexpr int NT = NC / 8;                 // n-tiles (8 or 4)
    constexpr int XS = 36;                     // row stride in u32 (64 halves + pad)
    __shared__ uint32_t Bf[4][NT][32][2];      // [ktile][ntile][lane][reg]
    __shared__ uint32_t Xs[128 * XS];

    int tid = threadIdx.x;
    int wid = tid >> 5, lane = tid & 31;
    int grp = lane >> 2;                       // 0..7
    int q   = lane & 3;                        // 0..3

    // Precompute B fragments: b_reg holds halves (k0, k0+1) at column n.
    for (int i = tid; i < 4 * NT * 32 * 2; i += 256) {
        int reg = i & 1;
        int ln  = (i >> 1) & 31;
        int nt  = (i >> 6) % NT;
        int kt  = (i >> 6) / NT;
        int k0 = kt * 16 + (ln & 3) * 2 + reg * 8;
        int n  = nt * 8 + (ln >> 2);
        __half2 h = __floats2half2_rn(W[k0 * NC + n], W[(k0 + 1) * NC + n]);
        Bf[kt][nt][ln][reg] = *(uint32_t*)&h;
    }

    int ntiles = (NN + 127) / 128;
    for (int tile = blockIdx.x; tile < ntiles; tile += gridDim.x) {
        int row0 = tile * 128;
        __syncthreads();
        for (int i = tid; i < 128 * 32; i += 256) {
            int r = i >> 5, c = i & 31;
            uint32_t v = 0;
            if (row0 + r < NN) {
                if constexpr (sizeof(InT) == 4) {
                    float2 f = __ldg((const float2*)in + (size_t)(row0 + r) * 32 + c);
                    __half2 h = __floats2half2_rn(f.x, f.y);
                    v = *(uint32_t*)&h;
                } else {
                    v = __ldg((const uint32_t*)in + (size_t)(row0 + r) * 32 + c);
                }
            }
            Xs[r * XS + c] = v;
        }
        __syncthreads();

        int rb = wid * 16;                     // warp's rows within tile
        float acc[NT][4];
#pragma unroll
        for (int nt = 0; nt < NT; nt++)
#pragma unroll
            for (int c = 0; c < 4; c++) acc[nt][c] = 0.f;

#pragma unroll
        for (int kt = 0; kt < 4; kt++) {
            uint32_t a0 = Xs[(rb + grp) * XS + kt * 8 + q];
            uint32_t a1 = Xs[(rb + grp + 8) * XS + kt * 8 + q];
            uint32_t a2 = Xs[(rb + grp) * XS + kt * 8 + 4 + q];
            uint32_t a3 = Xs[(rb + grp + 8) * XS + kt * 8 + 4 + q];
#pragma unroll
            for (int nt = 0; nt < NT; nt++) {
                uint32_t b0 = Bf[kt][nt][lane][0];
                uint32_t b1 = Bf[kt][nt][lane][1];
                MMA_16816(acc[nt][0], acc[nt][1], acc[nt][2], acc[nt][3],
                          a0, a1, a2, a3, b0, b1);
            }
        }

        int r0 = row0 + rb + grp;
        int r1 = r0 + 8;
        if constexpr (NC == 64) {
            float dv0 = (r0 < NN) ? __ldg(&g_dinv[r0]) : 0.f;
            float dv1 = (r1 < NN) ? __ldg(&g_dinv[r1]) : 0.f;
            if (!SCALE) { dv0 = 1.f; dv1 = 1.f; }
#pragma unroll
            for (int nt = 0; nt < NT; nt++) {
                int col = nt * 8 + q * 2;
                if (r0 < NN)
                    *(__half2*)((__half*)out + (size_t)r0 * NC + col) =
                        __floats2half2_rn(acc[nt][0] * dv0, acc[nt][1] * dv0);
                if (r1 < NN)
                    *(__half2*)((__half*)out + (size_t)r1 * NC + col) =
                        __floats2half2_rn(acc[nt][2] * dv1, acc[nt][3] * dv1);
            }
        } else {
#pragma unroll
            for (int nt = 0; nt < NT; nt++) {
                int col = nt * 8 + q * 2;
                float b0v = 0.f, b1v = 0.f;
                if (BIAS) { b0v = __ldg(&bias[col]); b1v = __ldg(&bias[col + 1]); }
                if (r0 < NN)
                    *(float2*)((float*)out + (size_t)r0 * NC + col) =
                        make_float2(acc[nt][0] + b0v, acc[nt][1] + b1v);
                if (r1 < NN)
                    *(float2*)((float*)out + (size_t)r1 * NC + col) =
                        make_float2(acc[nt][2] + b0v, acc[nt][3] + b1v);
            }
        }
    }
}

// ---------------- gather: 4 nodes/warp, 8 lanes x 8 dims ----------------
__global__ void __launch_bounds__(256) k_gather(const uint4* __restrict__ hw,
                                                const float* __restrict__ bias,
                                                uint4* __restrict__ hout) {
    int wrp  = blockIdx.x * 8 + (threadIdx.x >> 5);
    if (wrp * 4 >= NN) return;
    int lane = threadIdx.x & 31;
    int sub  = lane & 7;
    int node = wrp * 4 + (lane >> 3);

    uint4 sv = __ldg(&hw[node * 8 + sub]);
    float2 s0 = __half22float2(*(__half2*)&sv.x);
    float2 s1 = __half22float2(*(__half2*)&sv.y);
    float2 s2 = __half22float2(*(__half2*)&sv.z);
    float2 s3 = __half22float2(*(__half2*)&sv.w);
    float a0 = s0.x, a1 = s0.y, a2 = s1.x, a3 = s1.y;
    float a4 = s2.x, a5 = s2.y, a6 = s3.x, a7 = s3.y;

    int j   = g_rowptr[node];
    int end = g_rowptr[node + 1];
    while (__any_sync(~0u, j < end)) {
#pragma unroll
        for (int k = 0; k < 4; k++) {
            bool act = j < end;
            int jj = act ? j : 0;
            int c = __ldg(&g_col[jj]);
            float m = act ? 1.0f : 0.0f;
            uint4 u = __ldg(&hw[c * 8 + sub]);
            float2 g0 = __half22float2(*(__half2*)&u.x);
            float2 g1 = __half22float2(*(__half2*)&u.y);
            float2 g2 = __half22float2(*(__half2*)&u.z);
            float2 g3 = __half22float2(*(__half2*)&u.w);
            a0 = fmaf(m, g0.x, a0); a1 = fmaf(m, g0.y, a1);
            a2 = fmaf(m, g1.x, a2); a3 = fmaf(m, g1.y, a3);
            a4 = fmaf(m, g2.x, a4); a5 = fmaf(m, g2.y, a5);
            a6 = fmaf(m, g3.x, a6); a7 = fmaf(m, g3.y, a7);
            j++;
        }
    }

    float dv = __ldg(&g_dinv[node]);
    const float4* b4 = (const float4*)bias;
    float4 bl = b4[2 * sub], bh = b4[2 * sub + 1];
    a0 = fmaxf(fmaf(a0, dv, bl.x), 0.f);
    a1 = fmaxf(fmaf(a1, dv, bl.y), 0.f);
    a2 = fmaxf(fmaf(a2, dv, bl.z), 0.f);
    a3 = fmaxf(fmaf(a3, dv, bl.w), 0.f);
    a4 = fmaxf(fmaf(a4, dv, bh.x), 0.f);
    a5 = fmaxf(fmaf(a5, dv, bh.y), 0.f);
    a6 = fmaxf(fmaf(a6, dv, bh.z), 0.f);
    a7 = fmaxf(fmaf(a7, dv, bh.w), 0.f);
    uint4 o;
    *(__half2*)&o.x = __floats2half2_rn(a0, a1);
    *(__half2*)&o.y = __floats2half2_rn(a2, a3);
    *(__half2*)&o.z = __floats2half2_rn(a4, a5);
    *(__half2*)&o.w = __floats2half2_rn(a6, a7);
    hout[node * 8 + sub] = o;
}

// ---------------- launch ----------------
extern "C" void kernel_launch(void* const* d_in, const int* in_sizes, int n_in,
                              void* d_out, int out_size) {
    const float* x  = (const float*)d_in[0];
    const int*   ei = (const int*)d_in[1];
    const float* W1 = (const float*)d_in[2];
    const float* b1 = (const float*)d_in[3];
    const float* W2 = (const float*)d_in[4];
    const float* b2 = (const float*)d_in[5];
    const float* Wl = (const float*)d_in[6];
    const float* bl = (const float*)d_in[7];
    float*       out = (float*)d_out;

    __half* bufh; cudaGetSymbolAddress((void**)&bufh, g_bufh);
    __half* buf2; cudaGetSymbolAddress((void**)&buf2, g_buf2);

    static cudaStream_t s2 = nullptr;
    static cudaEvent_t evS = nullptr, evJ = nullptr;
    if (s2 == nullptr) {
        cudaStreamCreateWithFlags(&s2, cudaStreamNonBlocking);
        cudaEventCreateWithFlags(&evS, cudaEventDisableTiming);
        cudaEventCreateWithFlags(&evJ, cudaEventDisableTiming);
    }

    const int TB = 256;
    int gE2 = (NE / 2 + TB - 1) / TB;
    const int GATHER_GRID = (NN / 4 + 7) / 8;
    const int MMA_GRID = 296;

    // CSR build; gemm1 needs dinv -> fork after scan, overlapping fill
    k_count<<<gE2, TB>>>(ei);
    k_scan<<<SCAN_B, 1024>>>();
    cudaEventRecord(evS, 0);
    cudaStreamWaitEvent(s2, evS, 0);
    k_gemm_mma<64, float, __half, false, true><<<MMA_GRID, 256, 0, s2>>>(x, W1, nullptr, bufh);
    cudaEventRecord(evJ, s2);
    k_fill<<<gE2, TB>>>(ei);

    // join, then alternate gather / HMMA GEMM
    cudaStreamWaitEvent(0, evJ, 0);
    k_gather<<<GATHER_GRID, 256>>>((const uint4*)bufh, b1, (uint4*)buf2);
    k_gemm_mma<64, __half, __half, false, true><<<MMA_GRID, 256>>>(buf2, W2, nullptr, bufh);
    k_gather<<<GATHER_GRID, 256>>>((const uint4*)bufh, b2, (uint4*)buf2);
    k_gemm_mma<32, __half, float, true, false><<<MMA_GRID, 256>>>(buf2, Wl, bl, out);
}